// round 10
// baseline (speedup 1.0000x reference)
#include <cuda_runtime.h>
#include <cuda_bf16.h>

// PatchFFTLoss round 10: R9 math + persistent CTAs with dynamic work-stealing.
//  - grid = 888 resident CTAs (148 SMs x 6 CTAs); chunks (3072) pulled from a
//    global atomic counter -> no partial-wave tail, near-perfect SM balance.
//  - per-chunk partial goes to g_partials[chunk] (deterministic per chunk),
//    fixed-order final reduction -> bit-deterministic. Counters self-reset.
//  - math: thread pair = (input,target) of one patch; real-input 8x8 FFT,
//    Hermitian-in-v; f32x2-packed row FFTs and X1/X2 column FFTs; ortho
//    scale folded into the log argument.

#define NPATCH   (16 * 3 * 64 * 64)       // 196608
#define BLOCK    128
#define NCHUNK   (NPATCH * 2 / BLOCK)     // 3072 chunks of 128 threads
#define GRID     888                      // 148 SMs * 6 CTAs resident
#define LN2      0.69314718055994530942f
#define FINAL_SCALE ((LN2 * LN2) / (2.0f * 12582912.0f))
#define FULLM    0xffffffffu

__device__ float g_partials[NCHUNK];
__device__ unsigned int g_work = 0;
__device__ unsigned int g_done = 0;

typedef unsigned long long u64;

__device__ __forceinline__ u64 pk(float lo, float hi) {
    u64 r; asm("mov.b64 %0, {%1, %2};" : "=l"(r) : "f"(lo), "f"(hi)); return r;
}
__device__ __forceinline__ void upk(u64 v, float& lo, float& hi) {
    asm("mov.b64 {%0, %1}, %2;" : "=f"(lo), "=f"(hi) : "l"(v));
}
__device__ __forceinline__ u64 add2(u64 a, u64 b) {
    u64 r; asm("add.rn.f32x2 %0, %1, %2;" : "=l"(r) : "l"(a), "l"(b)); return r;
}
__device__ __forceinline__ u64 sub2(u64 a, u64 b) {
    u64 r; asm("sub.rn.f32x2 %0, %1, %2;" : "=l"(r) : "l"(a), "l"(b)); return r;
}
__device__ __forceinline__ u64 mul2(u64 a, u64 b) {
    u64 r; asm("mul.rn.f32x2 %0, %1, %2;" : "=l"(r) : "l"(a), "l"(b)); return r;
}

// g on unnormalized FFT value: sign(x) * log2(1 + |x|/8)
__device__ __forceinline__ float gfun(float x) {
    return copysignf(__log2f(fmaf(0.125f, fabsf(x), 1.0f)), x);
}

// squared difference of g across the (input,target) thread pair
__device__ __forceinline__ float dsq(float gv) {
    float gp = __shfl_xor_sync(FULLM, gv, 1);
    float d = gv - gp;
    return d * d;
}

// scalar complex 8-pt FFT in place, natural-order bins (validated r2-r9)
__device__ __forceinline__ void fft8c(float* xr, float* xi)
{
    const float C = 0.70710678118654752440f;
    float A0r=xr[0]+xr[4], A0i=xi[0]+xi[4];
    float A1r=xr[1]+xr[5], A1i=xi[1]+xi[5];
    float A2r=xr[2]+xr[6], A2i=xi[2]+xi[6];
    float A3r=xr[3]+xr[7], A3i=xi[3]+xi[7];
    float B0r=xr[0]-xr[4], B0i=xi[0]-xi[4];
    float d1r=xr[1]-xr[5], d1i=xi[1]-xi[5];
    float B1r=C*(d1r+d1i), B1i=C*(d1i-d1r);
    float B2r=xi[2]-xi[6], B2i=xr[6]-xr[2];
    float d3r=xr[3]-xr[7], d3i=xi[3]-xi[7];
    float B3r=C*(d3i-d3r), B3i=-C*(d3r+d3i);

    float A20r=A0r+A2r, A20i=A0i+A2i;
    float A22r=A0r-A2r, A22i=A0i-A2i;
    float A21r=A1r+A3r, A21i=A1i+A3i;
    float A23r=A1i-A3i, A23i=A3r-A1r;
    float B20r=B0r+B2r, B20i=B0i+B2i;
    float B22r=B0r-B2r, B22i=B0i-B2i;
    float B21r=B1r+B3r, B21i=B1i+B3i;
    float B23r=B1i-B3i, B23i=B3r-B1r;

    xr[0]=A20r+A21r; xi[0]=A20i+A21i;
    xr[4]=A20r-A21r; xi[4]=A20i-A21i;
    xr[2]=A22r+A23r; xi[2]=A22i+A23i;
    xr[6]=A22r-A23r; xi[6]=A22i-A23i;
    xr[1]=B20r+B21r; xi[1]=B20i+B21i;
    xr[5]=B20r-B21r; xi[5]=B20i-B21i;
    xr[3]=B22r+B23r; xi[3]=B22i+B23i;
    xr[7]=B22r-B23r; xi[7]=B22i-B23i;
}

// packed complex 8-pt FFT: each u64 holds the same butterfly slot of TWO
// independent FFTs (columns v=1 and v=2). Same network as fft8c.
__device__ __forceinline__ void fft8c2(u64* xr, u64* xi, u64 CC, u64 MCC)
{
    u64 A0r=add2(xr[0],xr[4]), A0i=add2(xi[0],xi[4]);
    u64 A1r=add2(xr[1],xr[5]), A1i=add2(xi[1],xi[5]);
    u64 A2r=add2(xr[2],xr[6]), A2i=add2(xi[2],xi[6]);
    u64 A3r=add2(xr[3],xr[7]), A3i=add2(xi[3],xi[7]);
    u64 B0r=sub2(xr[0],xr[4]), B0i=sub2(xi[0],xi[4]);
    u64 d1r=sub2(xr[1],xr[5]), d1i=sub2(xi[1],xi[5]);
    u64 B1r=mul2(CC,add2(d1r,d1i)), B1i=mul2(CC,sub2(d1i,d1r));
    u64 B2r=sub2(xi[2],xi[6]),      B2i=sub2(xr[6],xr[2]);
    u64 d3r=sub2(xr[3],xr[7]), d3i=sub2(xi[3],xi[7]);
    u64 B3r=mul2(CC,sub2(d3i,d3r)), B3i=mul2(MCC,add2(d3r,d3i));

    u64 A20r=add2(A0r,A2r), A20i=add2(A0i,A2i);
    u64 A22r=sub2(A0r,A2r), A22i=sub2(A0i,A2i);
    u64 A21r=add2(A1r,A3r), A21i=add2(A1i,A3i);
    u64 A23r=sub2(A1i,A3i), A23i=sub2(A3r,A1r);
    u64 B20r=add2(B0r,B2r), B20i=add2(B0i,B2i);
    u64 B22r=sub2(B0r,B2r), B22i=sub2(B0i,B2i);
    u64 B21r=add2(B1r,B3r), B21i=add2(B1i,B3i);
    u64 B23r=sub2(B1i,B3i), B23i=sub2(B3r,B1r);

    xr[0]=add2(A20r,A21r); xi[0]=add2(A20i,A21i);
    xr[4]=sub2(A20r,A21r); xi[4]=sub2(A20i,A21i);
    xr[2]=add2(A22r,A23r); xi[2]=add2(A22i,A23i);
    xr[6]=sub2(A22r,A23r); xi[6]=sub2(A22i,A23i);
    xr[1]=add2(B20r,B21r); xi[1]=add2(B20i,B21i);
    xr[5]=sub2(B20r,B21r); xi[5]=sub2(B20i,B21i);
    xr[3]=add2(B22r,B23r); xi[3]=add2(B22i,B23i);
    xr[7]=sub2(B22r,B23r); xi[7]=sub2(B22i,B23i);
}

// one chunk = 128 threads x (64 patch-pairs): returns this thread's acc
__device__ __forceinline__ float do_chunk(int chunk,
                                          const float* __restrict__ inp,
                                          const float* __restrict__ tgt)
{
    const int gid = chunk * BLOCK + threadIdx.x;
    const int t  = gid & 1;           // 0 = input, 1 = target
    const int p  = gid >> 1;          // patch index
    const int pw = p & 63;
    const int ph = (p >> 6) & 63;
    const int bc = p >> 12;
    const float* __restrict__ src = t ? tgt : inp;
    const size_t base = ((size_t)(bc * 512 + ph * 8)) * 512 + (size_t)pw * 8;

    const float C = 0.70710678118654752440f;
    const u64 CC  = pk(C, C);
    const u64 MCC = pk(-C, -C);

    // front-batched loads: 16 LDG.128
    float4 la[8], lb[8];
    #pragma unroll
    for (int r = 0; r < 8; r++) {
        const float* rp = src + base + (size_t)r * 512;
        la[r] = *(const float4*)(rp);
        lb[r] = *(const float4*)(rp + 4);
    }

    // packed real row FFTs: rows (2P, 2P+1) in one f32x2 lane-pair
    float R0[8], R4[8];
    float X1r[8], X1i[8], X2r[8], X2i[8], X3r[8], X3i[8];
    #pragma unroll
    for (int P = 0; P < 4; P++) {
        const int r0 = 2 * P, r1 = 2 * P + 1;
        u64 p0 = pk(la[r0].x, la[r1].x), p1 = pk(la[r0].y, la[r1].y);
        u64 p2 = pk(la[r0].z, la[r1].z), p3 = pk(la[r0].w, la[r1].w);
        u64 p4 = pk(lb[r0].x, lb[r1].x), p5 = pk(lb[r0].y, lb[r1].y);
        u64 p6 = pk(lb[r0].z, lb[r1].z), p7 = pk(lb[r0].w, lb[r1].w);

        u64 a04p = add2(p0, p4), a04m = sub2(p0, p4);
        u64 a26p = add2(p2, p6), a26m = sub2(p2, p6);
        u64 E0 = add2(a04p, a26p), E2 = sub2(a04p, a26p);
        u64 b15p = add2(p1, p5), b15m = sub2(p1, p5);
        u64 b37p = add2(p3, p7), b37m = sub2(p3, p7);
        u64 O0 = add2(b15p, b37p);
        u64 t1 = mul2(CC,  sub2(b15m, b37m));
        u64 t2 = mul2(MCC, add2(b15m, b37m));

        upk(add2(E0, O0),    R0[r0],  R0[r1]);
        upk(sub2(E0, O0),    R4[r0],  R4[r1]);
        upk(add2(a04m, t1),  X1r[r0], X1r[r1]);
        upk(sub2(t2, a26m),  X1i[r0], X1i[r1]);
        upk(E2,              X2r[r0], X2r[r1]);
        upk(sub2(b37p, b15p),X2i[r0], X2i[r1]);   // X2i = -O2
        upk(sub2(a04m, t1),  X3r[r0], X3r[r1]);
        upk(add2(a26m, t2),  X3i[r0], X3i[r1]);
    }

    float acc1 = 0.0f, acc2 = 0.0f;

    // columns v = 0 and v = 4: scalar real FFT, bins u = 0..4
    #pragma unroll
    for (int k = 0; k < 2; k++) {
        const float* c = k ? R4 : R0;
        float a04p=c[0]+c[4], a04m=c[0]-c[4];
        float a26p=c[2]+c[6], a26m=c[2]-c[6];
        float E0=a04p+a26p, E2=a04p-a26p;
        float b15p=c[1]+c[5], b15m=c[1]-c[5];
        float b37p=c[3]+c[7], b37m=c[3]-c[7];
        float O0=b15p+b37p, O2=b15p-b37p;
        float t1 =  C*(b15m-b37m);
        float t2 = -C*(b15m+b37m);
        acc1 += dsq(gfun(E0 + O0));
        acc1 += dsq(gfun(E0 - O0));
        acc2 += dsq(gfun(a04m + t1)) + dsq(gfun(-a26m + t2));
        acc2 += dsq(gfun(E2))        + dsq(gfun(-O2));
        acc2 += dsq(gfun(a04m - t1)) + dsq(gfun( a26m + t2));
    }

    // columns v = 1 and v = 2: ONE packed complex FFT (f32x2)
    {
        u64 xr[8], xi[8];
        #pragma unroll
        for (int r = 0; r < 8; r++) {
            xr[r] = pk(X1r[r], X2r[r]);
            xi[r] = pk(X1i[r], X2i[r]);
        }
        fft8c2(xr, xi, CC, MCC);
        #pragma unroll
        for (int u = 0; u < 8; u++) {
            float f1, f2, f3, f4;
            upk(xr[u], f1, f2);
            upk(xi[u], f3, f4);
            acc2 += dsq(gfun(f1)) + dsq(gfun(f3));
            acc2 += dsq(gfun(f2)) + dsq(gfun(f4));
        }
    }

    // column v = 3: scalar complex FFT
    fft8c(X3r, X3i);
    #pragma unroll
    for (int u = 0; u < 8; u++)
        acc2 += dsq(gfun(X3r[u])) + dsq(gfun(X3i[u]));

    return fmaf(2.0f, acc2, acc1);
}

__global__ void __launch_bounds__(BLOCK, 6)
patch_fft_loss_kernel(const float* __restrict__ inp,
                      const float* __restrict__ tgt,
                      float* __restrict__ out)
{
    __shared__ float smw[BLOCK / 32];
    __shared__ int   s_chunk;
    __shared__ bool  isLast;

    // persistent work-stealing loop over chunks
    while (true) {
        __syncthreads();                       // protect s_chunk reuse
        if (threadIdx.x == 0)
            s_chunk = (int)atomicAdd(&g_work, 1u);
        __syncthreads();
        const int chunk = s_chunk;
        if (chunk >= NCHUNK) break;

        float acc = do_chunk(chunk, inp, tgt);

        // deterministic block reduction -> per-chunk partial
        #pragma unroll
        for (int o = 16; o > 0; o >>= 1)
            acc += __shfl_xor_sync(FULLM, acc, o);
        if ((threadIdx.x & 31) == 0) smw[threadIdx.x >> 5] = acc;
        __syncthreads();
        if (threadIdx.x == 0) {
            float s = 0.0f;
            #pragma unroll
            for (int i = 0; i < BLOCK / 32; i++) s += smw[i];
            g_partials[chunk] = s;
        }
    }

    // CTA done: last CTA resets work counter and does the final reduction
    if (threadIdx.x == 0) {
        __threadfence();
        unsigned old = atomicInc(&g_done, GRID - 1);   // wraps to 0 on last
        isLast = (old == GRID - 1);
    }
    __syncthreads();

    if (isLast) {
        if (threadIdx.x == 0) g_work = 0;              // reset for next replay
        float a = 0.0f;
        for (int i = threadIdx.x; i < NCHUNK; i += BLOCK)
            a += __ldcg(&g_partials[i]);
        #pragma unroll
        for (int o = 16; o > 0; o >>= 1)
            a += __shfl_xor_sync(FULLM, a, o);
        if ((threadIdx.x & 31) == 0) smw[threadIdx.x >> 5] = a;
        __syncthreads();
        if (threadIdx.x == 0) {
            float s = 0.0f;
            #pragma unroll
            for (int i = 0; i < BLOCK / 32; i++) s += smw[i];
            out[0] = s * FINAL_SCALE;
        }
    }
}

extern "C" void kernel_launch(void* const* d_in, const int* in_sizes, int n_in,
                              void* d_out, int out_size)
{
    const float* inp = (const float*)d_in[0];
    const float* tgt = (const float*)d_in[1];
    patch_fft_loss_kernel<<<GRID, BLOCK>>>(inp, tgt, (float*)d_out);
}